// round 9
// baseline (speedup 1.0000x reference)
#include <cuda_runtime.h>
#include <stdint.h>

// preds: [32, 3, 640, 640] fp32
#define B_     32
#define H_     640
#define W_     640
#define HW_    (H_ * W_)          // 409600 floats per channel
#define TOPK_  1000
#define NB2    2048               // tail sort buckets
#define CAP    4096
#define TG     2.6f               // static fast-path threshold (p~0.0047 -> ~1900/img)
#define BX     25                 // blocks per image
#define TPB    256
#define NCHUNK 4                  // 4 x 16KB chunks per block (64KB)
#define CHUNKB 16384u             // bytes per chunk
#define CHUNKF 4096               // floats per chunk
#define STAGE  1024               // per-block staging slots

typedef unsigned long long ull;

// Device scratch (zero at load; kernel restores counters each execution)
__device__ ull g_cand[B_ * CAP];
__device__ ull g_sorted[B_ * CAP];
__device__ int g_count[B_];
__device__ int g_done[B_];

// Order-preserving bijection float -> uint (monotone increasing)
__device__ __forceinline__ unsigned int ordf(float x) {
    unsigned int u = __float_as_uint(x);
    return (u & 0x80000000u) ? ~u : (u | 0x80000000u);
}

__device__ __forceinline__ uint32_t smem_u32(const void* p) {
    uint32_t a;
    asm("{ .reg .u64 t; cvta.to.shared.u64 t, %1; cvt.u32.u64 %0, t; }"
        : "=r"(a) : "l"(p));
    return a;
}

__device__ __forceinline__ void mbar_init(uint32_t mbar, uint32_t cnt) {
    asm volatile("mbarrier.init.shared.b64 [%0], %1;" :: "r"(mbar), "r"(cnt) : "memory");
}

__device__ __forceinline__ void bulk_issue(uint32_t dst, const void* src, uint32_t mbar) {
    asm volatile("mbarrier.arrive.expect_tx.shared.b64 _, [%0], %1;"
                 :: "r"(mbar), "r"(CHUNKB) : "memory");
    asm volatile("cp.async.bulk.shared::cta.global.mbarrier::complete_tx::bytes "
                 "[%0], [%1], %2, [%3];"
                 :: "r"(dst), "l"(src), "r"(CHUNKB), "r"(mbar) : "memory");
}

__device__ __forceinline__ void mbar_wait(uint32_t mbar, uint32_t parity) {
    asm volatile(
        "{\n\t"
        ".reg .pred P;\n\t"
        "W%=:\n\t"
        "mbarrier.try_wait.parity.acquire.cta.shared::cta.b64 P, [%0], %1, 0x989680;\n\t"
        "@P bra D%=;\n\t"
        "bra W%=;\n\t"
        "D%=:\n\t"
        "}"
        :: "r"(mbar), "r"(parity) : "memory");
}

__global__ void __launch_bounds__(TPB) k_fused(const float* __restrict__ preds,
                                               float* __restrict__ out) {
    // 32 KB aliased: pass -> 2 x 16KB data buffers; tail -> hist[2048]+start[2048]
    __shared__ __align__(16) unsigned char big[32768];
    __shared__ __align__(16) ull stage[STAGE];           // 8 KB
    __shared__ __align__(8)  ull mbar[2];
    __shared__ unsigned int sh_part[TPB];
    __shared__ unsigned int sh_rmin[8], sh_rmax[8];
    __shared__ unsigned int sh_mn, sh_sh;
    __shared__ int sh_cnt, sh_base, sh_ovf, sh_flag, sh_T, sh_c2;

    const int b = blockIdx.x / BX;         // image
    const int x = blockIdx.x % BX;         // 64KB slice within image
    const int t = threadIdx.x;
    const int lane = t & 31;

    const float* chan = preds + (size_t)b * 3 * HW_;

    // ======================= PASS PHASE (bulk-copy pipeline) =======================
    {
        float4* dbuf0 = (float4*)big;            // 16 KB
        float4* dbuf1 = (float4*)(big + 16384);  // 16 KB
        const uint32_t d0 = smem_u32(dbuf0), d1 = smem_u32(dbuf1);
        const uint32_t mb0 = smem_u32(&mbar[0]), mb1 = smem_u32(&mbar[1]);

        if (t == 0) {
            sh_cnt = 0; sh_ovf = 0;
            mbar_init(mb0, 1);
            mbar_init(mb1, 1);
        }
        __syncthreads();

        const float* src0 = chan + (size_t)x * (NCHUNK * CHUNKF);
        if (t == 0) {
            bulk_issue(d0, src0,               mb0);
            bulk_issue(d1, src0 + CHUNKF,      mb1);
        }

        for (int c = 0; c < NCHUNK; c++) {
            const uint32_t par = (c >> 1) & 1;
            mbar_wait((c & 1) ? mb1 : mb0, par);
            const float4* sb = (c & 1) ? dbuf1 : dbuf0;

            float4 v[4];
#pragma unroll
            for (int i = 0; i < 4; i++) v[i] = sb[t + i * 256];

            unsigned int m = 0;
#pragma unroll
            for (int i = 0; i < 4; i++) {
                m |= (v[i].x >= TG) ? (1u << (4 * i + 0)) : 0u;
                m |= (v[i].y >= TG) ? (1u << (4 * i + 1)) : 0u;
                m |= (v[i].z >= TG) ? (1u << (4 * i + 2)) : 0u;
                m |= (v[i].w >= TG) ? (1u << (4 * i + 3)) : 0u;
            }

            const int nh = __popc(m);
            if (__ballot_sync(0xFFFFFFFFu, nh) != 0) {
                int pre = nh;
#pragma unroll
                for (int off = 1; off < 32; off <<= 1) {
                    int y = __shfl_up_sync(0xFFFFFFFFu, pre, off);
                    if (lane >= off) pre += y;
                }
                const int tot = __shfl_sync(0xFFFFFFFFu, pre, 31);
                int wbase = 0;
                if (lane == 31) wbase = atomicAdd(&sh_cnt, tot);
                wbase = __shfl_sync(0xFFFFFFFFu, wbase, 31);

                int pos = wbase + pre - nh;
                if (nh) {
                    // flat float index base of this chunk
                    const int cbase = x * (NCHUNK * CHUNKF) + c * CHUNKF;
#pragma unroll
                    for (int i = 0; i < 4; i++) {
                        const int fi = t + i * 256;        // float4 slot in chunk
                        const float f0 = v[i].x, f1 = v[i].y, f2 = v[i].z, f3 = v[i].w;
#pragma unroll
                        for (int k = 0; k < 4; k++) {
                            if (m & (1u << (4 * i + k))) {
                                if (pos < STAGE) {
                                    const float f = (k == 0) ? f0 : (k == 1) ? f1 : (k == 2) ? f2 : f3;
                                    const unsigned int o = ordf(f);
                                    const unsigned int idx = (unsigned int)(cbase + fi * 4 + k);
                                    stage[pos] = ((ull)o << 32) | (ull)(0xFFFFFFFFu - idx);
                                } else {
                                    sh_ovf = 1;
                                }
                                pos++;
                            }
                        }
                    }
                }
            }
            __syncthreads();   // all threads done reading this buffer
            if (t == 0 && c + 2 < NCHUNK) {
                bulk_issue((c & 1) ? d1 : d0, src0 + (size_t)(c + 2) * CHUNKF,
                           (c & 1) ? mb1 : mb0);
            }
        }

        // ONE global atomic per block; poison count on stage overflow
        if (t == 0) {
            int add = sh_cnt + (sh_ovf ? 1000000 : 0);
            sh_base = add ? atomicAdd(&g_count[b], add) : 0;
        }
        __syncthreads();

        const int cnt = min(sh_cnt, STAGE);
        const int base = sh_base;
        for (int i = t; i < cnt; i += TPB) {
            const int p = base + i;
            if (p < CAP) g_cand[b * CAP + p] = stage[i];
        }
    }

    // ===== DONE-COUNTER (release/acquire) =====
    __syncthreads();
    if (t == 0) {
        int old;
        asm volatile("atom.acq_rel.gpu.global.add.s32 %0, [%1], 1;"
                     : "=r"(old) : "l"(&g_done[b]) : "memory");
        sh_flag = (old == BX - 1);
    }
    __syncthreads();
    if (!sh_flag) return;

    unsigned int* hist  = (unsigned int*)big;            // 8 KB
    unsigned int* start = (unsigned int*)(big + 8192);   // 8 KB

    int M = g_count[b];

    // ============ FALLBACK (never taken for valid fast path) ============
    if (M < TOPK_ || M > CAP) {
        for (int i = t; i < NB2; i += TPB) hist[i] = 0u;
        if (t == 0) { sh_T = 0; sh_c2 = 0; }
        __syncthreads();

        const float4* sc = (const float4*)chan;
        for (int i = t; i < HW_ / 4; i += TPB) {
            const float4 w = sc[i];
            atomicAdd(&hist[ordf(w.x) >> 21], 1u);
            atomicAdd(&hist[ordf(w.y) >> 21], 1u);
            atomicAdd(&hist[ordf(w.z) >> 21], 1u);
            atomicAdd(&hist[ordf(w.w) >> 21], 1u);
        }
        __syncthreads();

        unsigned int seg = 0;
        for (int j = 7; j >= 0; j--) seg += hist[t * 8 + j];
        sh_part[t] = seg;
        __syncthreads();
        for (int off = 1; off < TPB; off <<= 1) {
            unsigned int vv = (t + off < TPB) ? sh_part[t + off] : 0u;
            __syncthreads();
            sh_part[t] += vv;
            __syncthreads();
        }
        unsigned int acc = sh_part[t] - seg;
        for (int j = 7; j >= 0; j--) {
            acc += hist[t * 8 + j];
            if (acc >= (unsigned)TOPK_) { atomicMax(&sh_T, t * 8 + j); break; }
        }
        __syncthreads();
        const unsigned int T = (unsigned int)sh_T;

        for (int i = t; i < HW_ / 4; i += TPB) {
            const float4 w = sc[i];
            const float f[4] = {w.x, w.y, w.z, w.w};
#pragma unroll
            for (int k = 0; k < 4; k++) {
                const unsigned int o = ordf(f[k]);
                if ((o >> 21) >= T) {
                    const int p = atomicAdd(&sh_c2, 1);
                    if (p < CAP) {
                        const unsigned int idx = (unsigned int)(i * 4 + k);
                        g_cand[b * CAP + p] = ((ull)o << 32) | (ull)(0xFFFFFFFFu - idx);
                    }
                }
            }
        }
        __syncthreads();
        M = min(sh_c2, CAP);
    }
    M = min(M, CAP);

    // ================= COUNTING SORT (descending) =================
    unsigned int lmin = 0xFFFFFFFFu, lmax = 0u;
    for (int i = t; i < M; i += TPB) {
        const unsigned int h = (unsigned int)(g_cand[b * CAP + i] >> 32);
        lmin = min(lmin, h);
        lmax = max(lmax, h);
    }
#pragma unroll
    for (int off = 16; off > 0; off >>= 1) {
        lmin = min(lmin, __shfl_down_sync(0xFFFFFFFFu, lmin, off));
        lmax = max(lmax, __shfl_down_sync(0xFFFFFFFFu, lmax, off));
    }
    if (lane == 0) { sh_rmin[t >> 5] = lmin; sh_rmax[t >> 5] = lmax; }
    for (int i = t; i < NB2; i += TPB) hist[i] = 0u;
    __syncthreads();
    if (t == 0) {
        unsigned int mn = 0xFFFFFFFFu, mx = 0u;
#pragma unroll
        for (int i = 0; i < 8; i++) { mn = min(mn, sh_rmin[i]); mx = max(mx, sh_rmax[i]); }
        const unsigned int range = mx - mn;
        const int bits = 32 - __clz(range | 1u);
        sh_sh = (bits > 11) ? (unsigned)(bits - 11) : 0u;
        sh_mn = mn;
    }
    __syncthreads();
    const unsigned int mn = sh_mn, shf = sh_sh;

    for (int i = t; i < M; i += TPB) {
        const unsigned int h = (unsigned int)(g_cand[b * CAP + i] >> 32);
        atomicAdd(&hist[(h - mn) >> shf], 1u);
    }
    __syncthreads();

    unsigned int seg = 0;
    for (int j = 7; j >= 0; j--) seg += hist[t * 8 + j];
    sh_part[t] = seg;
    __syncthreads();
    for (int off = 1; off < TPB; off <<= 1) {
        unsigned int vv = (t + off < TPB) ? sh_part[t + off] : 0u;
        __syncthreads();
        sh_part[t] += vv;
        __syncthreads();
    }
    unsigned int run = sh_part[t] - seg;
    for (int j = 7; j >= 0; j--) {
        start[t * 8 + j] = run;
        run += hist[t * 8 + j];
    }
    __syncthreads();

    for (int i = t; i < NB2; i += TPB) hist[i] = 0u;   // -> intra-bucket counters
    __syncthreads();

    for (int i = t; i < M; i += TPB) {
        const ull key = g_cand[b * CAP + i];
        const unsigned int bk = ((unsigned int)(key >> 32) - mn) >> shf;
        const unsigned int p = start[bk] + atomicAdd(&hist[bk], 1u);
        g_sorted[b * CAP + p] = key;
    }
    __syncthreads();

    // per-bucket insertion sort (descending) for buckets intersecting [0, TOPK)
    for (int bk = t; bk < NB2; bk += TPB) {
        const unsigned int c = hist[bk];
        if (c > 1u && start[bk] < (unsigned)TOPK_) {
            ull* s2 = &g_sorted[b * CAP + start[bk]];
            for (unsigned int a = 1; a < c; a++) {
                const ull kv = s2[a];
                int p2 = (int)a - 1;
                while (p2 >= 0 && s2[p2] < kv) { s2[p2 + 1] = s2[p2]; p2--; }
                s2[p2 + 1] = kv;
            }
        }
    }
    __syncthreads();

    // ================= EMIT =================
    const float* ph = chan + HW_;
    const float* pw = ph + HW_;
    float* boxes  = out;                              // [B, K, 4]
    float* scores = out + (size_t)B_ * TOPK_ * 4;     // [B, K]
    float* keep   = scores + (size_t)B_ * TOPK_;      // [B, K]

    for (int p = t; p < TOPK_; p += TPB) {
        const ull kk = g_sorted[b * CAP + p];
        const unsigned int o = (unsigned int)(kk >> 32);
        const unsigned int u = (o & 0x80000000u) ? (o ^ 0x80000000u) : ~o;
        const float score = __uint_as_float(u);
        const unsigned int idx = 0xFFFFFFFFu - (unsigned int)(kk & 0xFFFFFFFFull);

        const float h = fmaxf(ph[idx], 1e-6f) * (float)H_;
        const float w = fmaxf(pw[idx], 1e-6f) * (float)W_;
        const float cx = (float)(idx % W_);
        const float cy = (float)(idx / W_);

        float* bx = boxes + ((size_t)b * TOPK_ + p) * 4;
        bx[0] = cx - 0.5f * w;
        bx[1] = cy - 0.5f * h;
        bx[2] = cx + 0.5f * w;
        bx[3] = cy + 0.5f * h;
        scores[b * TOPK_ + p] = score;
        keep[b * TOPK_ + p]   = 1.0f;
    }

    if (t == 0) { g_count[b] = 0; g_done[b] = 0; }
}

// ---------------------------------------------------------------------------
extern "C" void kernel_launch(void* const* d_in, const int* in_sizes, int n_in,
                              void* d_out, int out_size) {
    const float* preds = (const float*)d_in[0];
    float* out = (float*)d_out;

    k_fused<<<B_ * BX, TPB>>>(preds, out);
}

// round 10
// speedup vs baseline: 1.1385x; 1.1385x over previous
#include <cuda_runtime.h>
#include <stdint.h>

// preds: [32, 3, 640, 640] fp32
#define B_     32
#define H_     640
#define W_     640
#define HW_    (H_ * W_)          // 409600 floats per channel
#define TOPK_  1000
#define NB2    2048               // tail sort buckets
#define CAP    4096
#define TG     2.6f               // static fast-path threshold (p~0.0047 -> ~1900/img)
#define BX     50                 // blocks per image (8192 floats each)
#define TPB    256
#define VEC    8                  // 8 x float4 per thread = 32 floats
#define STAGE  1024               // per-block staging slots

typedef unsigned long long ull;

// Device scratch (zero at load; kernel restores counters each execution)
__device__ ull g_cand[B_ * CAP];
__device__ ull g_sorted[B_ * CAP];
__device__ int g_count[B_];
__device__ int g_done[B_];

// Order-preserving bijection float -> uint (monotone increasing)
__device__ __forceinline__ unsigned int ordf(float x) {
    unsigned int u = __float_as_uint(x);
    return (u & 0x80000000u) ? ~u : (u | 0x80000000u);
}

__device__ __forceinline__ uint32_t smem_u32(const void* p) {
    uint32_t a;
    asm("{ .reg .u64 t; cvta.to.shared.u64 t, %1; cvt.u32.u64 %0, t; }"
        : "=r"(a) : "l"(p));
    return a;
}

__global__ void __launch_bounds__(TPB) k_fused(const float* __restrict__ preds,
                                               float* __restrict__ out) {
    // data buffer: 2048 float4 = 32 KB (pass); tail aliases hist/start over it
    __shared__ __align__(16) float4 data[2048];
    __shared__ __align__(16) ull stage[STAGE];           // 8 KB
    __shared__ unsigned int sh_part[TPB];
    __shared__ unsigned int sh_rmin[8], sh_rmax[8];
    __shared__ unsigned int sh_mn, sh_sh;
    __shared__ int sh_cnt, sh_base, sh_ovf, sh_flag, sh_T, sh_c2;

    const int b = blockIdx.x / BX;         // image
    const int x = blockIdx.x % BX;         // 8192-float slice within image
    const int t = threadIdx.x;
    const int lane = t & 31;

    const float* chan = preds + (size_t)b * 3 * HW_;

    // ======================= PASS PHASE (cp.async fire-and-forget) =======================
    {
        if (t == 0) { sh_cnt = 0; sh_ovf = 0; }

        const float4* __restrict__ src = (const float4*)chan + x * 2048;

        // Issue all 8 LDGSTS per thread — structurally in flight, no scoreboard.
#pragma unroll
        for (int j = 0; j < VEC; j++) {
            const uint32_t dst = smem_u32(&data[t + j * 256]);
            asm volatile("cp.async.cg.shared.global [%0], [%1], 16;"
                         :: "r"(dst), "l"(src + t + j * 256) : "memory");
        }
        asm volatile("cp.async.commit_group;" ::: "memory");
        asm volatile("cp.async.wait_group 0;" ::: "memory");
        __syncthreads();

        float4 v[VEC];
#pragma unroll
        for (int j = 0; j < VEC; j++) v[j] = data[t + j * 256];

        unsigned int m = 0;
#pragma unroll
        for (int j = 0; j < VEC; j++) {
            m |= (v[j].x >= TG) ? (1u << (4 * j + 0)) : 0u;
            m |= (v[j].y >= TG) ? (1u << (4 * j + 1)) : 0u;
            m |= (v[j].z >= TG) ? (1u << (4 * j + 2)) : 0u;
            m |= (v[j].w >= TG) ? (1u << (4 * j + 3)) : 0u;
        }

        const int nh = __popc(m);
        if (__ballot_sync(0xFFFFFFFFu, nh) != 0) {
            int pre = nh;
#pragma unroll
            for (int off = 1; off < 32; off <<= 1) {
                int y = __shfl_up_sync(0xFFFFFFFFu, pre, off);
                if (lane >= off) pre += y;
            }
            const int tot = __shfl_sync(0xFFFFFFFFu, pre, 31);
            int wbase = 0;
            if (lane == 31) wbase = atomicAdd(&sh_cnt, tot);   // shared atomic
            wbase = __shfl_sync(0xFFFFFFFFu, wbase, 31);

            int pos = wbase + pre - nh;
            if (nh) {
                const int cbase = x * 8192;                    // flat float base of slice
#pragma unroll
                for (int j = 0; j < VEC; j++) {
                    const int fi = t + j * 256;                // float4 slot in slice
                    const float f0 = v[j].x, f1 = v[j].y, f2 = v[j].z, f3 = v[j].w;
#pragma unroll
                    for (int k = 0; k < 4; k++) {
                        if (m & (1u << (4 * j + k))) {
                            if (pos < STAGE) {
                                const float f = (k == 0) ? f0 : (k == 1) ? f1 : (k == 2) ? f2 : f3;
                                const unsigned int o = ordf(f);
                                const unsigned int idx = (unsigned int)(cbase + fi * 4 + k);
                                stage[pos] = ((ull)o << 32) | (ull)(0xFFFFFFFFu - idx);
                            } else {
                                sh_ovf = 1;
                            }
                            pos++;
                        }
                    }
                }
            }
        }
        __syncthreads();

        // ONE global atomic per block; poison count on stage overflow
        if (t == 0) {
            int add = sh_cnt + (sh_ovf ? 1000000 : 0);
            sh_base = add ? atomicAdd(&g_count[b], add) : 0;
        }
        __syncthreads();

        const int cnt = min(sh_cnt, STAGE);
        const int base = sh_base;
        for (int i = t; i < cnt; i += TPB) {
            const int p = base + i;
            if (p < CAP) g_cand[b * CAP + p] = stage[i];
        }
    }

    // ===== DONE-COUNTER (release/acquire) =====
    __syncthreads();
    if (t == 0) {
        int old;
        asm volatile("atom.acq_rel.gpu.global.add.s32 %0, [%1], 1;"
                     : "=r"(old) : "l"(&g_done[b]) : "memory");
        sh_flag = (old == BX - 1);
    }
    __syncthreads();
    if (!sh_flag) return;

    unsigned int* hist  = (unsigned int*)data;            // 8 KB
    unsigned int* start = ((unsigned int*)data) + NB2;    // 8 KB

    int M = g_count[b];

    // ============ FALLBACK (never taken for valid fast path) ============
    if (M < TOPK_ || M > CAP) {
        for (int i = t; i < NB2; i += TPB) hist[i] = 0u;
        if (t == 0) { sh_T = 0; sh_c2 = 0; }
        __syncthreads();

        const float4* sc = (const float4*)chan;
        for (int i = t; i < HW_ / 4; i += TPB) {
            const float4 w = sc[i];
            atomicAdd(&hist[ordf(w.x) >> 21], 1u);
            atomicAdd(&hist[ordf(w.y) >> 21], 1u);
            atomicAdd(&hist[ordf(w.z) >> 21], 1u);
            atomicAdd(&hist[ordf(w.w) >> 21], 1u);
        }
        __syncthreads();

        unsigned int seg = 0;
        for (int j = 7; j >= 0; j--) seg += hist[t * 8 + j];
        sh_part[t] = seg;
        __syncthreads();
        for (int off = 1; off < TPB; off <<= 1) {
            unsigned int vv = (t + off < TPB) ? sh_part[t + off] : 0u;
            __syncthreads();
            sh_part[t] += vv;
            __syncthreads();
        }
        unsigned int acc = sh_part[t] - seg;
        for (int j = 7; j >= 0; j--) {
            acc += hist[t * 8 + j];
            if (acc >= (unsigned)TOPK_) { atomicMax(&sh_T, t * 8 + j); break; }
        }
        __syncthreads();
        const unsigned int T = (unsigned int)sh_T;

        for (int i = t; i < HW_ / 4; i += TPB) {
            const float4 w = sc[i];
            const float f[4] = {w.x, w.y, w.z, w.w};
#pragma unroll
            for (int k = 0; k < 4; k++) {
                const unsigned int o = ordf(f[k]);
                if ((o >> 21) >= T) {
                    const int p = atomicAdd(&sh_c2, 1);
                    if (p < CAP) {
                        const unsigned int idx = (unsigned int)(i * 4 + k);
                        g_cand[b * CAP + p] = ((ull)o << 32) | (ull)(0xFFFFFFFFu - idx);
                    }
                }
            }
        }
        __syncthreads();
        M = min(sh_c2, CAP);
    }
    M = min(M, CAP);

    // ================= COUNTING SORT (descending) =================
    unsigned int lmin = 0xFFFFFFFFu, lmax = 0u;
    for (int i = t; i < M; i += TPB) {
        const unsigned int h = (unsigned int)(g_cand[b * CAP + i] >> 32);
        lmin = min(lmin, h);
        lmax = max(lmax, h);
    }
#pragma unroll
    for (int off = 16; off > 0; off >>= 1) {
        lmin = min(lmin, __shfl_down_sync(0xFFFFFFFFu, lmin, off));
        lmax = max(lmax, __shfl_down_sync(0xFFFFFFFFu, lmax, off));
    }
    if (lane == 0) { sh_rmin[t >> 5] = lmin; sh_rmax[t >> 5] = lmax; }
    for (int i = t; i < NB2; i += TPB) hist[i] = 0u;
    __syncthreads();
    if (t == 0) {
        unsigned int mn = 0xFFFFFFFFu, mx = 0u;
#pragma unroll
        for (int i = 0; i < 8; i++) { mn = min(mn, sh_rmin[i]); mx = max(mx, sh_rmax[i]); }
        const unsigned int range = mx - mn;
        const int bits = 32 - __clz(range | 1u);
        sh_sh = (bits > 11) ? (unsigned)(bits - 11) : 0u;
        sh_mn = mn;
    }
    __syncthreads();
    const unsigned int mn = sh_mn, shf = sh_sh;

    for (int i = t; i < M; i += TPB) {
        const unsigned int h = (unsigned int)(g_cand[b * CAP + i] >> 32);
        atomicAdd(&hist[(h - mn) >> shf], 1u);
    }
    __syncthreads();

    unsigned int seg = 0;
    for (int j = 7; j >= 0; j--) seg += hist[t * 8 + j];
    sh_part[t] = seg;
    __syncthreads();
    for (int off = 1; off < TPB; off <<= 1) {
        unsigned int vv = (t + off < TPB) ? sh_part[t + off] : 0u;
        __syncthreads();
        sh_part[t] += vv;
        __syncthreads();
    }
    unsigned int run = sh_part[t] - seg;
    for (int j = 7; j >= 0; j--) {
        start[t * 8 + j] = run;
        run += hist[t * 8 + j];
    }
    __syncthreads();

    for (int i = t; i < NB2; i += TPB) hist[i] = 0u;   // -> intra-bucket counters
    __syncthreads();

    for (int i = t; i < M; i += TPB) {
        const ull key = g_cand[b * CAP + i];
        const unsigned int bk = ((unsigned int)(key >> 32) - mn) >> shf;
        const unsigned int p = start[bk] + atomicAdd(&hist[bk], 1u);
        g_sorted[b * CAP + p] = key;
    }
    __syncthreads();

    // per-bucket insertion sort (descending) for buckets intersecting [0, TOPK)
    for (int bk = t; bk < NB2; bk += TPB) {
        const unsigned int c = hist[bk];
        if (c > 1u && start[bk] < (unsigned)TOPK_) {
            ull* s2 = &g_sorted[b * CAP + start[bk]];
            for (unsigned int a = 1; a < c; a++) {
                const ull kv = s2[a];
                int p2 = (int)a - 1;
                while (p2 >= 0 && s2[p2] < kv) { s2[p2 + 1] = s2[p2]; p2--; }
                s2[p2 + 1] = kv;
            }
        }
    }
    __syncthreads();

    // ================= EMIT =================
    const float* ph = chan + HW_;
    const float* pw = ph + HW_;
    float* boxes  = out;                              // [B, K, 4]
    float* scores = out + (size_t)B_ * TOPK_ * 4;     // [B, K]
    float* keep   = scores + (size_t)B_ * TOPK_;      // [B, K]

    for (int p = t; p < TOPK_; p += TPB) {
        const ull kk = g_sorted[b * CAP + p];
        const unsigned int o = (unsigned int)(kk >> 32);
        const unsigned int u = (o & 0x80000000u) ? (o ^ 0x80000000u) : ~o;
        const float score = __uint_as_float(u);
        const unsigned int idx = 0xFFFFFFFFu - (unsigned int)(kk & 0xFFFFFFFFull);

        const float h = fmaxf(ph[idx], 1e-6f) * (float)H_;
        const float w = fmaxf(pw[idx], 1e-6f) * (float)W_;
        const float cx = (float)(idx % W_);
        const float cy = (float)(idx / W_);

        float* bx = boxes + ((size_t)b * TOPK_ + p) * 4;
        bx[0] = cx - 0.5f * w;
        bx[1] = cy - 0.5f * h;
        bx[2] = cx + 0.5f * w;
        bx[3] = cy + 0.5f * h;
        scores[b * TOPK_ + p] = score;
        keep[b * TOPK_ + p]   = 1.0f;
    }

    if (t == 0) { g_count[b] = 0; g_done[b] = 0; }
}

// ---------------------------------------------------------------------------
extern "C" void kernel_launch(void* const* d_in, const int* in_sizes, int n_in,
                              void* d_out, int out_size) {
    const float* preds = (const float*)d_in[0];
    float* out = (float*)d_out;

    k_fused<<<B_ * BX, TPB>>>(preds, out);
}

// round 11
// speedup vs baseline: 1.7608x; 1.5466x over previous
#include <cuda_runtime.h>
#include <stdint.h>

// preds: [32, 3, 640, 640] fp32
#define B_     32
#define H_     640
#define W_     640
#define HW_    (H_ * W_)          // 409600 floats per channel
#define TOPK_  1000
#define NB2    2048               // sort buckets
#define CAP    4096
#define TG     2.6f               // static fast-path threshold (p~0.0047 -> ~1900/img)
#define BX     100                // pass blocks per image (4096 floats each)
#define TPB    256
#define STAGE  1024

typedef unsigned long long ull;

// Device scratch (zero at load; k_select restores g_count each execution)
__device__ ull g_cand[B_ * CAP];
__device__ ull g_sorted[B_ * CAP];   // only used when M > 2048
__device__ int g_count[B_];

// Order-preserving bijection float -> uint (monotone increasing)
__device__ __forceinline__ unsigned int ordf(float x) {
    unsigned int u = __float_as_uint(x);
    return (u & 0x80000000u) ? ~u : (u | 0x80000000u);
}

// ---------------------------------------------------------------------------
// Kernel A: streaming pass. grid (100, 32) x 256.
// 4 x float4 per thread; hierarchical max -> 1 compare for the 86% no-hit case.
// Hits staged in shared; ONE global atomicAdd per block.
// key = (ordered_score << 32) | (0xFFFFFFFF - idx)  (desc == score desc, idx asc)
// ---------------------------------------------------------------------------
__global__ void __launch_bounds__(TPB) k_pass(const float* __restrict__ preds) {
    __shared__ __align__(16) ull stage[STAGE];   // 8 KB
    __shared__ int sh_cnt, sh_base, sh_ovf;

    const int b = blockIdx.y;
    const int t = threadIdx.x;
    const int lane = t & 31;

    if (t == 0) { sh_cnt = 0; sh_ovf = 0; }
    __syncthreads();

    const float4* __restrict__ sc = (const float4*)(preds + (size_t)b * 3 * HW_);
    const int tid = blockIdx.x * TPB + t;   // 0..25599

    float4 v[4];
#pragma unroll
    for (int j = 0; j < 4; j++) v[j] = sc[tid + j * 25600];

    // cheap rejection: max of 16 floats, one compare
    float mx = v[0].x;
#pragma unroll
    for (int j = 0; j < 4; j++) {
        mx = fmaxf(mx, fmaxf(fmaxf(v[j].x, v[j].y), fmaxf(v[j].z, v[j].w)));
    }

    unsigned int m = 0;
    if (mx >= TG) {
#pragma unroll
        for (int j = 0; j < 4; j++) {
            m |= (v[j].x >= TG) ? (1u << (4 * j + 0)) : 0u;
            m |= (v[j].y >= TG) ? (1u << (4 * j + 1)) : 0u;
            m |= (v[j].z >= TG) ? (1u << (4 * j + 2)) : 0u;
            m |= (v[j].w >= TG) ? (1u << (4 * j + 3)) : 0u;
        }
    }

    const int nh = __popc(m);
    if (__ballot_sync(0xFFFFFFFFu, nh) != 0) {
        int pre = nh;
#pragma unroll
        for (int off = 1; off < 32; off <<= 1) {
            int y = __shfl_up_sync(0xFFFFFFFFu, pre, off);
            if (lane >= off) pre += y;
        }
        const int tot = __shfl_sync(0xFFFFFFFFu, pre, 31);
        int wbase = 0;
        if (lane == 31) wbase = atomicAdd(&sh_cnt, tot);   // shared atomic
        wbase = __shfl_sync(0xFFFFFFFFu, wbase, 31);

        int pos = wbase + pre - nh;
        if (nh) {
#pragma unroll
            for (int j = 0; j < 4; j++) {
                const int i4 = tid + j * 25600;
                const float f0 = v[j].x, f1 = v[j].y, f2 = v[j].z, f3 = v[j].w;
#pragma unroll
                for (int k = 0; k < 4; k++) {
                    if (m & (1u << (4 * j + k))) {
                        if (pos < STAGE) {
                            const float f = (k == 0) ? f0 : (k == 1) ? f1 : (k == 2) ? f2 : f3;
                            const unsigned int o = ordf(f);
                            const unsigned int idx = (unsigned int)(i4 * 4 + k);
                            stage[pos] = ((ull)o << 32) | (ull)(0xFFFFFFFFu - idx);
                        } else {
                            sh_ovf = 1;
                        }
                        pos++;
                    }
                }
            }
        }
    }
    __syncthreads();

    if (t == 0) {
        int add = sh_cnt + (sh_ovf ? 1000000 : 0);   // poison on overflow
        sh_base = add ? atomicAdd(&g_count[b], add) : 0;
    }
    __syncthreads();

    const int cnt = min(sh_cnt, STAGE);
    const int base = sh_base;
    for (int i = t; i < cnt; i += TPB) {
        const int p = base + i;
        if (p < CAP) g_cand[b * CAP + p] = stage[i];
    }
}

// ---------------------------------------------------------------------------
// Kernel B: per-image select. grid 32 x 1024 threads.
// Counting sort with keys scattered into SHARED (M <= 2048; global fallback
// otherwise), per-bucket insertion sorts at LDS latency, emit, counter reset.
// ---------------------------------------------------------------------------
__global__ void __launch_bounds__(1024) k_select(const float* __restrict__ preds,
                                                 float* __restrict__ out) {
    __shared__ __align__(16) ull ssort[2048];        // 16 KB
    __shared__ unsigned int hist[NB2];               // 8 KB
    __shared__ unsigned int start[NB2];              // 8 KB
    __shared__ unsigned int part[1024];              // 4 KB
    __shared__ unsigned int sh_rmin[32], sh_rmax[32];
    __shared__ unsigned int sh_mn, sh_sh;
    __shared__ int sh_T, sh_c2;

    const int b = blockIdx.x;
    const int t = threadIdx.x;
    const int lane = t & 31;

    const float* chan = preds + (size_t)b * 3 * HW_;

    int M = g_count[b];

    // ============ FALLBACK (never taken for valid fast path) ============
    if (M < TOPK_ || M > CAP) {
        for (int i = t; i < NB2; i += 1024) hist[i] = 0u;
        if (t == 0) { sh_T = 0; sh_c2 = 0; }
        __syncthreads();

        const float4* sc = (const float4*)chan;
        for (int i = t; i < HW_ / 4; i += 1024) {
            const float4 w = sc[i];
            atomicAdd(&hist[ordf(w.x) >> 21], 1u);
            atomicAdd(&hist[ordf(w.y) >> 21], 1u);
            atomicAdd(&hist[ordf(w.z) >> 21], 1u);
            atomicAdd(&hist[ordf(w.w) >> 21], 1u);
        }
        __syncthreads();

        const unsigned int p2 = hist[2 * t] + hist[2 * t + 1];
        part[t] = p2;
        __syncthreads();
        for (int off = 1; off < 1024; off <<= 1) {
            unsigned int vv = (t + off < 1024) ? part[t + off] : 0u;
            __syncthreads();
            part[t] += vv;
            __syncthreads();
        }
        unsigned int acc = part[t] - p2;
        for (int j = 1; j >= 0; j--) {
            acc += hist[2 * t + j];
            if (acc >= (unsigned)TOPK_) { atomicMax(&sh_T, 2 * t + j); break; }
        }
        __syncthreads();
        const unsigned int T = (unsigned int)sh_T;

        for (int i = t; i < HW_ / 4; i += 1024) {
            const float4 w = sc[i];
            const float f[4] = {w.x, w.y, w.z, w.w};
#pragma unroll
            for (int k = 0; k < 4; k++) {
                const unsigned int o = ordf(f[k]);
                if ((o >> 21) >= T) {
                    const int p = atomicAdd(&sh_c2, 1);
                    if (p < CAP) {
                        const unsigned int idx = (unsigned int)(i * 4 + k);
                        g_cand[b * CAP + p] = ((ull)o << 32) | (ull)(0xFFFFFFFFu - idx);
                    }
                }
            }
        }
        __syncthreads();
        M = min(sh_c2, CAP);
    }
    M = min(M, CAP);

    // keys live in SHARED when M <= 2048 (overwhelmingly common); else global
    ull* kbuf = (M <= 2048) ? ssort : &g_sorted[b * CAP];

    // ---- min/max of candidate high words ----
    unsigned int lmin = 0xFFFFFFFFu, lmax = 0u;
    for (int i = t; i < M; i += 1024) {
        const unsigned int h = (unsigned int)(g_cand[b * CAP + i] >> 32);
        lmin = min(lmin, h);
        lmax = max(lmax, h);
    }
#pragma unroll
    for (int off = 16; off > 0; off >>= 1) {
        lmin = min(lmin, __shfl_down_sync(0xFFFFFFFFu, lmin, off));
        lmax = max(lmax, __shfl_down_sync(0xFFFFFFFFu, lmax, off));
    }
    if (lane == 0) { sh_rmin[t >> 5] = lmin; sh_rmax[t >> 5] = lmax; }
    for (int i = t; i < NB2; i += 1024) hist[i] = 0u;
    __syncthreads();
    if (t == 0) {
        unsigned int mn = 0xFFFFFFFFu, mx = 0u;
#pragma unroll
        for (int i = 0; i < 32; i++) { mn = min(mn, sh_rmin[i]); mx = max(mx, sh_rmax[i]); }
        const unsigned int range = mx - mn;
        const int bits = 32 - __clz(range | 1u);
        sh_sh = (bits > 11) ? (unsigned)(bits - 11) : 0u;
        sh_mn = mn;
    }
    __syncthreads();
    const unsigned int mn = sh_mn, shf = sh_sh;

    // ---- bucket histogram ----
    for (int i = t; i < M; i += 1024) {
        const unsigned int h = (unsigned int)(g_cand[b * CAP + i] >> 32);
        atomicAdd(&hist[(h - mn) >> shf], 1u);
    }
    __syncthreads();

    // ---- suffix scan: start[bk] = #elements in strictly higher buckets ----
    const unsigned int p2 = hist[2 * t] + hist[2 * t + 1];
    part[t] = p2;
    __syncthreads();
    for (int off = 1; off < 1024; off <<= 1) {
        unsigned int vv = (t + off < 1024) ? part[t + off] : 0u;
        __syncthreads();
        part[t] += vv;
        __syncthreads();
    }
    unsigned int run = part[t] - p2;
    start[2 * t + 1] = run;
    start[2 * t]     = run + hist[2 * t + 1];
    __syncthreads();

    for (int i = t; i < NB2; i += 1024) hist[i] = 0u;   // -> intra-bucket counters
    __syncthreads();

    // ---- scatter (coalesced global read -> shared write) ----
    for (int i = t; i < M; i += 1024) {
        const ull key = g_cand[b * CAP + i];
        const unsigned int bk = ((unsigned int)(key >> 32) - mn) >> shf;
        const unsigned int p = start[bk] + atomicAdd(&hist[bk], 1u);
        kbuf[p] = key;
    }
    __syncthreads();

    // ---- per-bucket insertion sort (descending) for buckets touching [0, TOPK) ----
    for (int bk = t; bk < NB2; bk += 1024) {
        const unsigned int c = hist[bk];
        if (c > 1u && start[bk] < (unsigned)TOPK_) {
            ull* s2 = &kbuf[start[bk]];
            for (unsigned int a = 1; a < c; a++) {
                const ull kv = s2[a];
                int q = (int)a - 1;
                while (q >= 0 && s2[q] < kv) { s2[q + 1] = s2[q]; q--; }
                s2[q + 1] = kv;
            }
        }
    }
    __syncthreads();

    // ---- emit ----
    const float* ph = chan + HW_;
    const float* pw = ph + HW_;
    float* boxes  = out;                              // [B, K, 4]
    float* scores = out + (size_t)B_ * TOPK_ * 4;     // [B, K]
    float* keep   = scores + (size_t)B_ * TOPK_;      // [B, K]

    if (t < TOPK_) {
        const ull kk = kbuf[t];
        const unsigned int o = (unsigned int)(kk >> 32);
        const unsigned int u = (o & 0x80000000u) ? (o ^ 0x80000000u) : ~o;
        const float score = __uint_as_float(u);
        const unsigned int idx = 0xFFFFFFFFu - (unsigned int)(kk & 0xFFFFFFFFull);

        const float h = fmaxf(ph[idx], 1e-6f) * (float)H_;
        const float w = fmaxf(pw[idx], 1e-6f) * (float)W_;
        const float cx = (float)(idx % W_);
        const float cy = (float)(idx / W_);

        float* bx = boxes + ((size_t)b * TOPK_ + t) * 4;
        bx[0] = cx - 0.5f * w;
        bx[1] = cy - 0.5f * h;
        bx[2] = cx + 0.5f * w;
        bx[3] = cy + 0.5f * h;
        scores[b * TOPK_ + t] = score;
        keep[b * TOPK_ + t]   = 1.0f;
    }

    if (t == 0) g_count[b] = 0;   // reset for next graph replay
}

// ---------------------------------------------------------------------------
extern "C" void kernel_launch(void* const* d_in, const int* in_sizes, int n_in,
                              void* d_out, int out_size) {
    const float* preds = (const float*)d_in[0];
    float* out = (float*)d_out;

    dim3 gp(BX, B_);
    k_pass<<<gp, TPB>>>(preds);
    k_select<<<B_, 1024>>>(preds, out);
}